// round 5
// baseline (speedup 1.0000x reference)
#include <cuda_runtime.h>
#include <math.h>

#define Bn 8
#define Tn 512
#define Nn 64
#define Hn 8
#define Mt 64
#define PREDn 96
#define HIDn 256

#define TWO_PI 6.283185307179586
typedef unsigned long long ull;

// ---------------- f32x2 helpers ----------------
__device__ __forceinline__ ull ffma2(ull a, ull b, ull c) {
    ull d;
    asm("fma.rn.f32x2 %0, %1, %2, %3;" : "=l"(d) : "l"(a), "l"(b), "l"(c));
    return d;
}
__device__ __forceinline__ ull pack2(float x, float y) {
    ull r;
    asm("mov.b64 %0, {%1, %2};" : "=l"(r) : "f"(x), "f"(y));
    return r;
}
__device__ __forceinline__ float2 unpack2(ull v) {
    float2 r;
    asm("mov.b64 {%0, %1}, %2;" : "=f"(r.x), "=f"(r.y) : "l"(v));
    return r;
}

// ---------------- device scratch ----------------
__device__ float  d_res[Bn*Tn*Nn];
__device__ float  d_trend[Bn*Tn*Nn];
__device__ float  d_trend_out[Bn*PREDn*Nn];
__device__ float  d_G2[Bn*Tn*Nn*Hn];       // (b,t,(n,h)) : 512 cols per (b,t)

// precomputed small params
__device__ float  d_cabs[Hn];
__device__ float  d_C[Hn][Hn][Hn];         // [hp][h1][h2]
__device__ float  d_Otil[Hn][Hn];          // [hp][h2]
__device__ float2 d_TW64[64];
__device__ float2 d_TW512[512];
__device__ ull    d_TWp[512];              // packed (cos, -sin)
__device__ float  d_Cw[Mt*PREDn], d_Sw[Mt*PREDn];

// ---------------- setup ----------------
__global__ void k_setup_small(const float* __restrict__ emb,
                              const float* __restrict__ cWq, const float* __restrict__ cWk,
                              const float* __restrict__ cWv, const float* __restrict__ cWo,
                              const float* __restrict__ tWq, const float* __restrict__ tWk,
                              const float* __restrict__ tWv, const float* __restrict__ tWo,
                              const float* __restrict__ dr_w)
{
    __shared__ float eq[128], ek[128], ev[128];
    __shared__ float P[8][128];
    __shared__ float Qg[8][128], Kg[8][128], Vg[8][128];
    __shared__ float wod[128];
    int t = threadIdx.x; // 1024 threads

    if (t < 64) {
        double a = TWO_PI * (double)t / 64.0;
        d_TW64[t] = make_float2((float)cos(a), (float)sin(a));
    }
    if (t < 512) {
        double a = TWO_PI * (double)t / 512.0;
        float c = (float)cos(a), s = (float)sin(a);
        d_TW512[t] = make_float2(c, s);
        d_TWp[t] = pack2(c, -s);
    }

    if (t < 128) {
        float aq = 0.f, ak = 0.f, av = 0.f;
        for (int d = 0; d < 128; d++) {
            float e = emb[d];
            aq = fmaf(e, cWq[d*128 + t], aq);
            ak = fmaf(e, cWk[d*128 + t], ak);
            av = fmaf(e, cWv[d*128 + t], av);
        }
        eq[t] = aq; ek[t] = ak; ev[t] = av;
        float s = 0.f;
        for (int e = 0; e < 128; e++) s = fmaf(tWo[t*128 + e], dr_w[e], s);
        wod[t] = s;
    }
    __syncthreads();

    if (t < 8) {
        float c = 0.f;
        for (int d = 0; d < 16; d++) c = fmaf(eq[t*16 + d], ek[t*16 + d], c);
        d_cabs[t] = fabsf(c);
    }
    {
        int h = t >> 7, e = t & 127;
        float s = 0.f;
        for (int d = 0; d < 16; d++) s = fmaf(ev[h*16 + d], cWo[(h*16 + d)*128 + e], s);
        P[h][e] = s;
    }
    __syncthreads();

    {
        int h = t >> 7, e = t & 127;
        float sq = 0.f, sk = 0.f, sv = 0.f;
        for (int d = 0; d < 128; d++) {
            float p = P[h][d];
            sq = fmaf(p, tWq[d*128 + e], sq);
            sk = fmaf(p, tWk[d*128 + e], sk);
            sv = fmaf(p, tWv[d*128 + e], sv);
        }
        Qg[h][e] = sq; Kg[h][e] = sk; Vg[h][e] = sv;
    }
    __syncthreads();

    if (t < 512) {
        int hp = t >> 6, h1 = (t >> 3) & 7, h2 = t & 7;
        float s = 0.f;
        for (int d = 0; d < 16; d++) s = fmaf(Qg[h1][hp*16 + d], Kg[h2][hp*16 + d], s);
        d_C[hp][h1][h2] = s;
    }
    if (t >= 512 && t < 576) {
        int u = t - 512;
        int hp = u >> 3, h2 = u & 7;
        float s = 0.f;
        for (int d = 0; d < 16; d++) s = fmaf(Vg[h2][hp*16 + d], wod[hp*16 + d], s);
        d_Otil[hp][h2] = s;
    }
}

__global__ void k_setup_cwsw(const float* __restrict__ out_w)
{
    int tau = blockIdx.x, p = threadIdx.x; // 64 blocks x 96 threads
    float c = 0.f, s = 0.f;
    int k = 0;
    #pragma unroll 4
    for (int t = 0; t < 512; t++) {
        float w = out_w[t*PREDn + p];
        float2 tw = d_TW512[k];
        c = fmaf(tw.x, w, c);
        s = fmaf(tw.y, w, s);
        k = (k + tau) & 511;
    }
    d_Cw[tau*PREDn + p] = c;
    d_Sw[tau*PREDn + p] = s;
}

// ---------------- decomposition ----------------
__global__ void k_decomp(const float* __restrict__ x,
                         const float* __restrict__ dec_w, const float* __restrict__ dec_b)
{
    __shared__ float xs[80][64];
    int b = blockIdx.y, t0 = blockIdx.x * 32;
    int tid = threadIdx.x;
    const float* xb = x + b*Tn*Nn;

    for (int i = tid; i < 80*64; i += 512) {
        int row = i >> 6, col = i & 63;
        int tg = t0 - 24 + row;
        tg = tg < 0 ? 0 : (tg > 511 ? 511 : tg);
        xs[row][col] = xb[tg*64 + col];
    }
    __syncthreads();

    float w0 = dec_w[0], w1v = dec_w[1], bb0 = dec_b[0], bb1 = dec_b[1];
    int c = tid >> 6, n = tid & 63;
    int r0 = c * 4;
    float s49 = 0.f, s17 = 0.f;
    #pragma unroll
    for (int j = 0; j < 49; j++) {
        float v = xs[r0 + j][n];
        s49 += v;
        if (j >= 16 && j <= 32) s17 += v;
    }
    #pragma unroll
    for (int s = 0; s < 4; s++) {
        if (s > 0) {
            s49 += xs[r0 + 48 + s][n] - xs[r0 + s - 1][n];
            s17 += xs[r0 + 32 + s][n] - xs[r0 + 15 + s][n];
        }
        float xv = xs[r0 + 24 + s][n];
        float m17 = s17 * (1.f/17.f), m49 = s49 * (1.f/49.f);
        float l0 = fmaf(xv, w0, bb0);
        float l1 = fmaf(xv, w1v, bb1);
        float mx = fmaxf(l0, l1);
        float e0 = __expf(l0 - mx), e1 = __expf(l1 - mx);
        float tr = (m17*e0 + m49*e1) / (e0 + e1);
        int gi = b*Tn*Nn + (t0 + r0 + s)*64 + n;
        d_trend[gi] = tr;
        d_res[gi]   = xv - tr;
    }
}

// ---------------- fused trend MLP: 8 rows per block through all 3 layers ----------------
// grid 64 blocks, 256 threads. Rows are (b, n0..n0+7). All layers in smem.
__global__ void __launch_bounds__(256) k_mlp(const float* __restrict__ w1, const float* __restrict__ b1,
                                             const float* __restrict__ w2, const float* __restrict__ b2,
                                             const float* __restrict__ w3, const float* __restrict__ b3)
{
    __shared__ __align__(16) float A[512][8];    // input rows (also reused as L3 partials)
    __shared__ __align__(16) float H1[256][8];
    __shared__ __align__(16) float H2[256][8];

    int br = blockIdx.x;
    int b = br >> 3, n0 = (br & 7) * 8;
    int tid = threadIdx.x;

    for (int i = tid; i < 1024; i += 256) {
        int t = i >> 1, j = (i & 1) * 4;
        *(float4*)&A[t][j] = *(const float4*)&d_trend[b*32768 + t*64 + n0 + j];
    }
    __syncthreads();

    // ---- L1: h1 = relu(A^T @ w1 + b1), thread = output column c ----
    {
        int c = tid;
        float bias = b1[c];
        ull acc0 = pack2(bias, bias), acc1 = acc0, acc2 = acc0, acc3 = acc0;
        #pragma unroll 8
        for (int k = 0; k < 512; k++) {
            float w = __ldg(&w1[k*256 + c]);
            ull wv = pack2(w, w);
            ulonglong2 a01 = *(const ulonglong2*)&A[k][0];
            ulonglong2 a23 = *(const ulonglong2*)&A[k][4];
            acc0 = ffma2(a01.x, wv, acc0);
            acc1 = ffma2(a01.y, wv, acc1);
            acc2 = ffma2(a23.x, wv, acc2);
            acc3 = ffma2(a23.y, wv, acc3);
        }
        float2 v;
        v = unpack2(acc0); H1[c][0] = fmaxf(v.x, 0.f); H1[c][1] = fmaxf(v.y, 0.f);
        v = unpack2(acc1); H1[c][2] = fmaxf(v.x, 0.f); H1[c][3] = fmaxf(v.y, 0.f);
        v = unpack2(acc2); H1[c][4] = fmaxf(v.x, 0.f); H1[c][5] = fmaxf(v.y, 0.f);
        v = unpack2(acc3); H1[c][6] = fmaxf(v.x, 0.f); H1[c][7] = fmaxf(v.y, 0.f);
    }
    __syncthreads();

    // ---- L2: h2 = relu(h1 @ w2 + b2) ----
    {
        int c = tid;
        float bias = b2[c];
        ull acc0 = pack2(bias, bias), acc1 = acc0, acc2 = acc0, acc3 = acc0;
        #pragma unroll 8
        for (int k = 0; k < 256; k++) {
            float w = __ldg(&w2[k*256 + c]);
            ull wv = pack2(w, w);
            ulonglong2 a01 = *(const ulonglong2*)&H1[k][0];
            ulonglong2 a23 = *(const ulonglong2*)&H1[k][4];
            acc0 = ffma2(a01.x, wv, acc0);
            acc1 = ffma2(a01.y, wv, acc1);
            acc2 = ffma2(a23.x, wv, acc2);
            acc3 = ffma2(a23.y, wv, acc3);
        }
        float2 v;
        v = unpack2(acc0); H2[c][0] = fmaxf(v.x, 0.f); H2[c][1] = fmaxf(v.y, 0.f);
        v = unpack2(acc1); H2[c][2] = fmaxf(v.x, 0.f); H2[c][3] = fmaxf(v.y, 0.f);
        v = unpack2(acc2); H2[c][4] = fmaxf(v.x, 0.f); H2[c][5] = fmaxf(v.y, 0.f);
        v = unpack2(acc3); H2[c][6] = fmaxf(v.x, 0.f); H2[c][7] = fmaxf(v.y, 0.f);
    }
    __syncthreads();

    // ---- L3: out = h2 @ w3 + b3, split-k over 2 halves, 192 threads ----
    float* Pp = &A[0][0];   // reuse A as [96][8] partial buffer
    ull acc0 = pack2(0.f, 0.f), acc1 = acc0, acc2 = acc0, acc3 = acc0;
    int c = tid % 96, half = tid / 96;
    if (tid < 192) {
        int k0 = half * 128;
        #pragma unroll 8
        for (int k = 0; k < 128; k++) {
            float w = __ldg(&w3[(k0 + k)*96 + c]);
            ull wv = pack2(w, w);
            ulonglong2 a01 = *(const ulonglong2*)&H2[k0 + k][0];
            ulonglong2 a23 = *(const ulonglong2*)&H2[k0 + k][4];
            acc0 = ffma2(a01.x, wv, acc0);
            acc1 = ffma2(a01.y, wv, acc1);
            acc2 = ffma2(a23.x, wv, acc2);
            acc3 = ffma2(a23.y, wv, acc3);
        }
        if (half == 1) {
            float2 v;
            v = unpack2(acc0); Pp[c*8+0] = v.x; Pp[c*8+1] = v.y;
            v = unpack2(acc1); Pp[c*8+2] = v.x; Pp[c*8+3] = v.y;
            v = unpack2(acc2); Pp[c*8+4] = v.x; Pp[c*8+5] = v.y;
            v = unpack2(acc3); Pp[c*8+6] = v.x; Pp[c*8+7] = v.y;
        }
    }
    __syncthreads();
    if (tid < 96) {
        float bias = b3[c];
        float o[8];
        float2 v;
        v = unpack2(acc0); o[0] = v.x; o[1] = v.y;
        v = unpack2(acc1); o[2] = v.x; o[3] = v.y;
        v = unpack2(acc2); o[4] = v.x; o[5] = v.y;
        v = unpack2(acc3); o[6] = v.x; o[7] = v.y;
        #pragma unroll
        for (int j = 0; j < 8; j++) o[j] += Pp[c*8 + j] + bias;
        float4* dst = (float4*)&d_trend_out[(b*PREDn + c)*Nn + n0];
        dst[0] = make_float4(o[0], o[1], o[2], o[3]);
        dst[1] = make_float4(o[4], o[5], o[6], o[7]);
    }
}

// ---------------- CEM (unchanged, known-good) ----------------
__global__ void k_cem() // 256 threads, grid Bn*Tn
{
    __shared__ float  resv[64];
    __shared__ float2 tw2[64];
    __shared__ float2 Fs[32];
    __shared__ float  aMag[32];
    __shared__ float2 part[4][32];
    __shared__ float2 g2s[32][8];
    __shared__ float  sMaxA;
    int bt = blockIdx.x;
    int tid = threadIdx.x;

    if (tid < 64) { resv[tid] = d_res[bt*64 + tid]; tw2[tid] = d_TW64[tid]; }
    __syncthreads();

    if (tid < 128) {
        int m = tid & 31, q = tid >> 5;
        float re = 0.f, im = 0.f;
        int k = (m * (q*16)) & 63;
        #pragma unroll
        for (int j = 0; j < 16; j++) {
            float v = resv[q*16 + j];
            float2 t = tw2[k];
            re = fmaf(v,  t.x, re);
            im = fmaf(v, -t.y, im);
            k = (k + m) & 63;
        }
        part[q][m] = make_float2(re, im);
    }
    __syncthreads();
    if (tid < 32) {
        float2 p0 = part[0][tid], p1 = part[1][tid], p2 = part[2][tid], p3 = part[3][tid];
        float re = p0.x + p1.x + p2.x + p3.x;
        float im = p0.y + p1.y + p2.y + p3.y;
        Fs[tid] = make_float2(re, im);
        float mag = sqrtf(re*re + im*im);
        aMag[tid] = mag;
        #pragma unroll
        for (int o = 16; o; o >>= 1) mag = fmaxf(mag, __shfl_xor_sync(0xffffffffu, mag, o));
        if (tid == 0) sMaxA = mag;
    }
    __syncthreads();

    {
        int h = tid >> 5, m = tid & 31;
        float scale = aMag[m] * d_cabs[h] * 0.25f;
        float mA = sMaxA;
        float denom = 0.f, gre = 0.f, gim = 0.f;
        #pragma unroll 4
        for (int n = 0; n < 32; n++) {
            float p = __expf(scale * (aMag[n] - mA));
            float2 F = Fs[n];
            denom += p;
            gre = fmaf(p, F.x, gre);
            gim = fmaf(p, F.y, gim);
        }
        float sc = (m == 0 ? 1.f : 2.f) / (64.f * denom);
        g2s[m][h] = make_float2(gre * sc, -gim * sc);
    }
    __syncthreads();

    {
        int h = tid & 7, nb = tid >> 3;
        float acc0 = g2s[0][h].x, acc1 = acc0;
        int k = 0;
        #pragma unroll 4
        for (int m = 1; m < 32; m++) {
            k = (k + nb) & 63;
            int k2 = (k + ((m & 1) << 5)) & 63;
            float2 g  = g2s[m][h];
            float2 ta = tw2[k];
            float2 tb = tw2[k2];
            acc0 = fmaf(g.x, ta.x, acc0); acc0 = fmaf(g.y, ta.y, acc0);
            acc1 = fmaf(g.x, tb.x, acc1); acc1 = fmaf(g.y, tb.y, acc1);
        }
        d_G2[bt*512 + nb*8 + h]      = acc0;
        d_G2[bt*512 + (nb+32)*8 + h] = acc1;
    }
}

// ---------------- fused TEM: rfft + attention + output, 2 n per block ----------------
__global__ void __launch_bounds__(256) k_tem(const float* __restrict__ dr_b,
                                             const float* __restrict__ out_b,
                                             const float* __restrict__ wf,
                                             float* __restrict__ out)
{
    __shared__ __align__(16) ull sd[256*16];
    __shared__ ull twp[512];
    __shared__ float Csh[8][8][8];
    __shared__ float Osh[8][8];

    float* HreT = (float*)sd;                      // [2][8][66]
    float* HimT = HreT + 2*8*66;                   // [2][8][66]
    ull*   zpk  = (ull*)(HimT + 2*8*66);           // [2][64][8]
    float* zsm  = (float*)(zpk + 2*64*8);          // [2][64][2]

    int ng = blockIdx.x, b = blockIdx.y;
    int c0 = ng * 16;
    int tid = threadIdx.x;

    for (int i = tid; i < 512; i += 256) twp[i] = d_TWp[i];
    for (int i = tid; i < 512; i += 256) ((float*)Csh)[i] = ((const float*)d_C)[i];
    if (tid < 64) ((float*)Osh)[tid] = ((const float*)d_Otil)[tid];

    // phase A: fold t <-> 512-t into packed (s,d)
    for (int i = tid; i < 1024; i += 256) {
        int t = i >> 2, cc = (i & 3) * 4;
        int tb = (t == 0) ? 256 : 512 - t;
        float4 ga = *(const float4*)&d_G2[(b*512 + t )*512 + c0 + cc];
        float4 gb = *(const float4*)&d_G2[(b*512 + tb)*512 + c0 + cc];
        if (t == 0) {
            sd[cc+0] = pack2(ga.x, gb.x); sd[cc+1] = pack2(ga.y, gb.y);
            sd[cc+2] = pack2(ga.z, gb.z); sd[cc+3] = pack2(ga.w, gb.w);
        } else {
            sd[t*16+cc+0] = pack2(ga.x + gb.x, ga.x - gb.x);
            sd[t*16+cc+1] = pack2(ga.y + gb.y, ga.y - gb.y);
            sd[t*16+cc+2] = pack2(ga.z + gb.z, ga.z - gb.z);
            sd[t*16+cc+3] = pack2(ga.w + gb.w, ga.w - gb.w);
        }
    }
    __syncthreads();

    // phase B: DFT into registers. thread = (tau 0..63, 4 cols), vectorized LDS.128
    int tau = tid >> 2, cq = (tid & 3) * 4;
    ull acc[4];
    {
        float sgn = (tau & 1) ? -1.f : 1.f;
        #pragma unroll
        for (int j = 0; j < 4; j++) {
            float2 sd0 = unpack2(sd[cq + j]);
            acc[j] = pack2(fmaf(sgn, sd0.y, sd0.x), 0.f);
        }
    }
    {
        int k = tau;
        #pragma unroll 4
        for (int t = 1; t < 256; t++) {
            ull w = twp[k];
            ulonglong2 p0 = *(const ulonglong2*)&sd[t*16 + cq];
            ulonglong2 p1 = *(const ulonglong2*)&sd[t*16 + cq + 2];
            acc[0] = ffma2(p0.x, w, acc[0]);
            acc[1] = ffma2(p0.y, w, acc[1]);
            acc[2] = ffma2(p1.x, w, acc[2]);
            acc[3] = ffma2(p1.y, w, acc[3]);
            k = (k + tau) & 511;
        }
    }
    __syncthreads();

    #pragma unroll
    for (int j = 0; j < 4; j++) {
        int col = cq + j, nl = col >> 3, h = col & 7;
        float2 v = unpack2(acc[j]);
        HreT[(nl*8 + h)*66 + tau] = v.x;
        HimT[(nl*8 + h)*66 + tau] = v.y;
    }
    __syncthreads();

    // zeta
    for (int i = tid; i < 2*64*8; i += 256) {
        int nl = i >> 9, np = (i >> 3) & 63, hp = i & 7;
        float zr = 0.f, zi = 0.f;
        #pragma unroll
        for (int h2 = 0; h2 < 8; h2++) {
            float o = Osh[hp][h2];
            zr = fmaf(HreT[(nl*8 + h2)*66 + np], o, zr);
            zi = fmaf(HimT[(nl*8 + h2)*66 + np], o, zi);
        }
        zpk[(nl*64 + np)*8 + hp] = pack2(zr, zi);
    }
    __syncthreads();

    // attention
    int mq = tid >> 3, hp = tid & 7;
    #pragma unroll
    for (int nl = 0; nl < 2; nl++) {
        const float* HreB = HreT + nl*8*66;
        const float* HimB = HimT + nl*8*66;
        #pragma unroll
        for (int mi = 0; mi < 2; mi++) {
            int m = mq + mi*32;
            float uR[8], uI[8];
            #pragma unroll
            for (int h2 = 0; h2 < 8; h2++) { uR[h2] = 0.f; uI[h2] = 0.f; }
            #pragma unroll
            for (int h1 = 0; h1 < 8; h1++) {
                float hr = HreB[h1*66 + m], hi = HimB[h1*66 + m];
                #pragma unroll
                for (int h2 = 0; h2 < 8; h2++) {
                    float c = Csh[hp][h1][h2];
                    uR[h2] = fmaf(hr, c, uR[h2]);
                    uI[h2] = fmaf(hi, c, uI[h2]);
                }
            }
            ull uR2[8], uI2[8], nuR2[8];
            #pragma unroll
            for (int h2 = 0; h2 < 8; h2++) {
                uR2[h2]  = pack2(uR[h2],  uR[h2]);
                uI2[h2]  = pack2(uI[h2],  uI[h2]);
                nuR2[h2] = pack2(-uR[h2], -uR[h2]);
            }

            float mrun = -1e30f, lrun = 0.f;
            ull az = pack2(0.f, 0.f);
            const ull* zrow = zpk + nl*64*8 + hp;

            for (int npq = 0; npq < 32; npq++) {
                ull sr2 = pack2(0.f, 0.f), si2 = pack2(0.f, 0.f);
                #pragma unroll
                for (int h2 = 0; h2 < 8; h2++) {
                    ull hr2 = ((const ull*)(HreB + h2*66))[npq];
                    ull hi2 = ((const ull*)(HimB + h2*66))[npq];
                    sr2 = ffma2(hr2, uR2[h2], sr2);
                    sr2 = ffma2(hi2, uI2[h2], sr2);
                    si2 = ffma2(hr2, uI2[h2], si2);
                    si2 = ffma2(hi2, nuR2[h2], si2);
                }
                float2 sr = unpack2(sr2), si = unpack2(si2);
                float sc0 = sqrtf(fmaf(sr.x, sr.x, si.x*si.x)) * 0.25f;
                float sc1 = sqrtf(fmaf(sr.y, sr.y, si.y*si.y)) * 0.25f;
                ull z0 = zrow[(2*npq)*8], z1 = zrow[(2*npq+1)*8];
                {
                    float mnew = fmaxf(mrun, sc0);
                    float corr = __expf(mrun - mnew);
                    float p    = __expf(sc0 - mnew);
                    lrun = fmaf(lrun, corr, p);
                    az = ffma2(az, pack2(corr, corr), ffma2(z0, pack2(p, p), pack2(0.f, 0.f)));
                    mrun = mnew;
                }
                {
                    float mnew = fmaxf(mrun, sc1);
                    float corr = __expf(mrun - mnew);
                    float p    = __expf(sc1 - mnew);
                    lrun = fmaf(lrun, corr, p);
                    az = ffma2(az, pack2(corr, corr), ffma2(z1, pack2(p, p), pack2(0.f, 0.f)));
                    mrun = mnew;
                }
            }
            float inv = 1.f / lrun;
            float2 a = unpack2(az);
            float ar = a.x * inv, ai = a.y * inv;
            #pragma unroll
            for (int off = 4; off >= 1; off >>= 1) {
                ar += __shfl_down_sync(0xffffffffu, ar, off, 8);
                ai += __shfl_down_sync(0xffffffffu, ai, off, 8);
            }
            if (hp == 0) {
                zsm[(nl*64 + m)*2 + 0] = ar;
                zsm[(nl*64 + m)*2 + 1] = ai;
            }
        }
    }
    __syncthreads();

    // final: irfft fold + trend fuse
    if (tid < 192) {
        int nl = tid / 96, p = tid % 96;
        float acc2 = zsm[nl*128] * d_Cw[p];
        #pragma unroll 4
        for (int tu = 1; tu < 64; tu++) {
            acc2 = fmaf( 2.f*zsm[(nl*64 + tu)*2 + 0], d_Cw[tu*PREDn + p], acc2);
            acc2 = fmaf(-2.f*zsm[(nl*64 + tu)*2 + 1], d_Sw[tu*PREDn + p], acc2);
        }
        float xo = acc2 * (1.f/512.f) + dr_b[0]*d_Cw[p] + out_b[p];
        int n = ng*2 + nl;
        float v = wf[0]*xo + wf[1]*d_trend_out[(b*PREDn + p)*Nn + n];
        out[(b*PREDn + p)*Nn + n] = v;
    }
}

// ---------------- stream/event context ----------------
namespace {
struct GpuCtx {
    cudaStream_t s1 = nullptr;
    cudaEvent_t eFork = nullptr, eRes = nullptr, eG3 = nullptr;
    bool ok = false;
    GpuCtx() {
        ok = (cudaStreamCreateWithFlags(&s1, cudaStreamNonBlocking) == cudaSuccess) &&
             (cudaEventCreateWithFlags(&eFork, cudaEventDisableTiming) == cudaSuccess) &&
             (cudaEventCreateWithFlags(&eRes,  cudaEventDisableTiming) == cudaSuccess) &&
             (cudaEventCreateWithFlags(&eG3,   cudaEventDisableTiming) == cudaSuccess);
    }
};
GpuCtx g_ctx;
}

// ---------------- launch ----------------
extern "C" void kernel_launch(void* const* d_in, const int* in_sizes, int n_in,
                              void* d_out, int out_size)
{
    const float* x      = (const float*)d_in[0];
    const float* emb    = (const float*)d_in[1];
    const float* dec_w  = (const float*)d_in[2];
    const float* dec_b  = (const float*)d_in[3];
    const float* mlp_w1 = (const float*)d_in[4];
    const float* mlp_b1 = (const float*)d_in[5];
    const float* mlp_w2 = (const float*)d_in[6];
    const float* mlp_b2 = (const float*)d_in[7];
    const float* mlp_w3 = (const float*)d_in[8];
    const float* mlp_b3 = (const float*)d_in[9];
    const float* cWq    = (const float*)d_in[10];
    const float* cWk    = (const float*)d_in[11];
    const float* cWv    = (const float*)d_in[12];
    const float* cWo    = (const float*)d_in[13];
    const float* tWq    = (const float*)d_in[14];
    const float* tWk    = (const float*)d_in[15];
    const float* tWv    = (const float*)d_in[16];
    const float* tWo    = (const float*)d_in[17];
    const float* dr_w   = (const float*)d_in[18];
    const float* dr_b   = (const float*)d_in[19];
    const float* out_w  = (const float*)d_in[20];
    const float* out_b  = (const float*)d_in[21];
    const float* W_fuse = (const float*)d_in[22];
    float* out = (float*)d_out;

    if (g_ctx.ok) {
        cudaStream_t s1 = g_ctx.s1;
        cudaEventRecord(g_ctx.eFork, 0);
        cudaStreamWaitEvent(s1, g_ctx.eFork, 0);

        // main stream: frequency-branch prep
        k_setup_small<<<1, 1024>>>(emb, cWq, cWk, cWv, cWo, tWq, tWk, tWv, tWo, dr_w);
        k_setup_cwsw<<<64, 96>>>(out_w);

        // side stream: trend branch (decomp -> fused MLP)
        k_decomp<<<dim3(16, 8), 512, 0, s1>>>(x, dec_w, dec_b);
        cudaEventRecord(g_ctx.eRes, s1);
        k_mlp<<<64, 256, 0, s1>>>(mlp_w1, mlp_b1, mlp_w2, mlp_b2, mlp_w3, mlp_b3);
        cudaEventRecord(g_ctx.eG3, s1);

        // main stream: cem after res is ready
        cudaStreamWaitEvent(0, g_ctx.eRes, 0);
        k_cem<<<Bn*Tn, 256>>>();
        cudaStreamWaitEvent(0, g_ctx.eG3, 0);
        k_tem<<<dim3(32, 8), 256>>>(dr_b, out_b, W_fuse, out);
    } else {
        k_setup_small<<<1, 1024>>>(emb, cWq, cWk, cWv, cWo, tWq, tWk, tWv, tWo, dr_w);
        k_setup_cwsw<<<64, 96>>>(out_w);
        k_decomp<<<dim3(16, 8), 512>>>(x, dec_w, dec_b);
        k_mlp<<<64, 256>>>(mlp_w1, mlp_b1, mlp_w2, mlp_b2, mlp_w3, mlp_b3);
        k_cem<<<Bn*Tn, 256>>>();
        k_tem<<<dim3(32, 8), 256>>>(dr_b, out_b, W_fuse, out);
    }
}

// round 6
// speedup vs baseline: 1.1220x; 1.1220x over previous
#include <cuda_runtime.h>
#include <math.h>

#define Bn 8
#define Tn 512
#define Nn 64
#define Hn 8
#define Mt 64
#define PREDn 96
#define HIDn 256

#define TWO_PI 6.283185307179586
typedef unsigned long long ull;

// ---------------- f32x2 helpers ----------------
__device__ __forceinline__ ull ffma2(ull a, ull b, ull c) {
    ull d;
    asm("fma.rn.f32x2 %0, %1, %2, %3;" : "=l"(d) : "l"(a), "l"(b), "l"(c));
    return d;
}
__device__ __forceinline__ ull pack2(float x, float y) {
    ull r;
    asm("mov.b64 %0, {%1, %2};" : "=l"(r) : "f"(x), "f"(y));
    return r;
}
__device__ __forceinline__ float2 unpack2(ull v) {
    float2 r;
    asm("mov.b64 {%0, %1}, %2;" : "=f"(r.x), "=f"(r.y) : "l"(v));
    return r;
}

// ---------------- device scratch ----------------
__device__ float  d_res[Bn*Tn*Nn];
__device__ float  d_trend[Bn*Tn*Nn];
__device__ float  d_h1[512*256];
__device__ float  d_h2[512*256];
__device__ float  d_trend_out[Bn*PREDn*Nn];
__device__ float  d_G2[Bn*Tn*Nn*Hn];       // (b,t,(n,h))
__device__ float2 d_z[Bn*Nn*Mt];           // (b,n,tau)

// precomputed small params
__device__ float  d_cabs[Hn];
__device__ float  d_C[Hn][Hn][Hn];
__device__ float  d_Otil[Hn][Hn];
__device__ float2 d_TW64[64];
__device__ float2 d_TW512[512];
__device__ ull    d_TWp[512];
__device__ float  d_Cw[Mt*PREDn], d_Sw[Mt*PREDn];

// ---------------- setupA: twiddles + cabs (feeds cem + tem DFT + cwsw) ----------------
__global__ void k_setupA(const float* __restrict__ emb,
                         const float* __restrict__ cWq, const float* __restrict__ cWk)
{
    __shared__ float eq[128], ek[128];
    int t = threadIdx.x; // 512 threads

    if (t < 64) {
        double a = TWO_PI * (double)t / 64.0;
        d_TW64[t] = make_float2((float)cos(a), (float)sin(a));
    }
    {
        double a = TWO_PI * (double)t / 512.0;
        float c = (float)cos(a), s = (float)sin(a);
        d_TW512[t] = make_float2(c, s);
        d_TWp[t] = pack2(c, -s);
    }
    if (t < 128) {
        float aq = 0.f, ak = 0.f;
        #pragma unroll 4
        for (int d = 0; d < 128; d++) {
            float e = emb[d];
            aq = fmaf(e, cWq[d*128 + t], aq);
            ak = fmaf(e, cWk[d*128 + t], ak);
        }
        eq[t] = aq; ek[t] = ak;
    }
    __syncthreads();
    if (t < 8) {
        float c = 0.f;
        #pragma unroll
        for (int d = 0; d < 16; d++) c = fmaf(eq[t*16 + d], ek[t*16 + d], c);
        d_cabs[t] = fabsf(c);
    }
}

// ---------------- setupB: C / Otil (feeds tem only; independent of setupA) ----------------
__global__ void k_setupB(const float* __restrict__ emb,
                         const float* __restrict__ cWv, const float* __restrict__ cWo,
                         const float* __restrict__ tWq, const float* __restrict__ tWk,
                         const float* __restrict__ tWv, const float* __restrict__ tWo,
                         const float* __restrict__ dr_w)
{
    __shared__ float ev[128], wod[128];
    __shared__ float P[8][128];
    __shared__ float Qg[8][128], Kg[8][128], Vg[8][128];
    int t = threadIdx.x; // 1024 threads

    if (t < 128) {
        float av = 0.f;
        #pragma unroll 4
        for (int d = 0; d < 128; d++) av = fmaf(emb[d], cWv[d*128 + t], av);
        ev[t] = av;
        float s = 0.f;
        #pragma unroll 4
        for (int e = 0; e < 128; e++) s = fmaf(tWo[t*128 + e], dr_w[e], s);
        wod[t] = s;
    }
    __syncthreads();

    {
        int h = t >> 7, e = t & 127;
        float s = 0.f;
        #pragma unroll
        for (int d = 0; d < 16; d++) s = fmaf(ev[h*16 + d], cWo[(h*16 + d)*128 + e], s);
        P[h][e] = s;
    }
    __syncthreads();

    {
        int h = t >> 7, e = t & 127;
        float sq = 0.f, sk = 0.f, sv = 0.f;
        #pragma unroll 4
        for (int d = 0; d < 128; d++) {
            float p = P[h][d];
            sq = fmaf(p, tWq[d*128 + e], sq);
            sk = fmaf(p, tWk[d*128 + e], sk);
            sv = fmaf(p, tWv[d*128 + e], sv);
        }
        Qg[h][e] = sq; Kg[h][e] = sk; Vg[h][e] = sv;
    }
    __syncthreads();

    if (t < 512) {
        int hp = t >> 6, h1 = (t >> 3) & 7, h2 = t & 7;
        float s = 0.f;
        #pragma unroll
        for (int d = 0; d < 16; d++) s = fmaf(Qg[h1][hp*16 + d], Kg[h2][hp*16 + d], s);
        d_C[hp][h1][h2] = s;
    }
    if (t >= 512 && t < 576) {
        int u = t - 512;
        int hp = u >> 3, h2 = u & 7;
        float s = 0.f;
        #pragma unroll
        for (int d = 0; d < 16; d++) s = fmaf(Vg[h2][hp*16 + d], wod[hp*16 + d], s);
        d_Otil[hp][h2] = s;
    }
}

__global__ void k_setup_cwsw(const float* __restrict__ out_w)
{
    int tau = blockIdx.x, p = threadIdx.x; // 64 blocks x 96 threads
    float c = 0.f, s = 0.f;
    int k = 0;
    #pragma unroll 4
    for (int t = 0; t < 512; t++) {
        float w = out_w[t*PREDn + p];
        float2 tw = d_TW512[k];
        c = fmaf(tw.x, w, c);
        s = fmaf(tw.y, w, s);
        k = (k + tau) & 511;
    }
    d_Cw[tau*PREDn + p] = c;
    d_Sw[tau*PREDn + p] = s;
}

// ---------------- decomposition ----------------
__global__ void k_decomp(const float* __restrict__ x,
                         const float* __restrict__ dec_w, const float* __restrict__ dec_b)
{
    __shared__ float xs[80][64];
    int b = blockIdx.y, t0 = blockIdx.x * 32;
    int tid = threadIdx.x;
    const float* xb = x + b*Tn*Nn;

    for (int i = tid; i < 80*64; i += 512) {
        int row = i >> 6, col = i & 63;
        int tg = t0 - 24 + row;
        tg = tg < 0 ? 0 : (tg > 511 ? 511 : tg);
        xs[row][col] = xb[tg*64 + col];
    }
    __syncthreads();

    float w0 = dec_w[0], w1v = dec_w[1], bb0 = dec_b[0], bb1 = dec_b[1];
    int c = tid >> 6, n = tid & 63;
    int r0 = c * 4;
    float s49 = 0.f, s17 = 0.f;
    #pragma unroll
    for (int j = 0; j < 49; j++) {
        float v = xs[r0 + j][n];
        s49 += v;
        if (j >= 16 && j <= 32) s17 += v;
    }
    #pragma unroll
    for (int s = 0; s < 4; s++) {
        if (s > 0) {
            s49 += xs[r0 + 48 + s][n] - xs[r0 + s - 1][n];
            s17 += xs[r0 + 32 + s][n] - xs[r0 + 15 + s][n];
        }
        float xv = xs[r0 + 24 + s][n];
        float m17 = s17 * (1.f/17.f), m49 = s49 * (1.f/49.f);
        float l0 = fmaf(xv, w0, bb0);
        float l1 = fmaf(xv, w1v, bb1);
        float mx = fmaxf(l0, l1);
        float e0 = __expf(l0 - mx), e1 = __expf(l1 - mx);
        float tr = (m17*e0 + m49*e1) / (e0 + e1);
        int gi = b*Tn*Nn + (t0 + r0 + s)*64 + n;
        d_trend[gi] = tr;
        d_res[gi]   = xv - tr;
    }
}

// ---------------- MLP GEMMs (R3 proven versions) ----------------
__global__ void k_gemm1(const float* __restrict__ w1, const float* __restrict__ b1)
{
    __shared__ float As[32][36];
    __shared__ float Ws[32][36];
    int r0 = blockIdx.y * 32, c0 = blockIdx.x * 32;
    int b = r0 >> 6, n0 = r0 & 32;
    int tid = threadIdx.x;
    int lr = tid >> 3, l4 = (tid & 7) * 4;
    int ty = tid >> 4, cy = tid & 15;

    float2 bias = *(const float2*)&b1[c0 + 2*cy];
    float a00 = bias.x, a01 = bias.y, a10 = bias.x, a11 = bias.y;

    float4 ra = *(const float4*)&d_trend[b*32768 + lr*64 + n0 + l4];
    float4 rw = *(const float4*)&w1[lr*256 + c0 + l4];

    for (int kt = 0; kt < 16; kt++) {
        *(float4*)&As[lr][l4] = ra;
        *(float4*)&Ws[lr][l4] = rw;
        __syncthreads();
        if (kt < 15) {
            int kg = (kt+1)*32 + lr;
            ra = *(const float4*)&d_trend[b*32768 + kg*64 + n0 + l4];
            rw = *(const float4*)&w1[kg*256 + c0 + l4];
        }
        #pragma unroll
        for (int k = 0; k < 32; k++) {
            float2 a = *(const float2*)&As[k][2*ty];
            float2 w = *(const float2*)&Ws[k][2*cy];
            a00 = fmaf(a.x, w.x, a00); a01 = fmaf(a.x, w.y, a01);
            a10 = fmaf(a.y, w.x, a10); a11 = fmaf(a.y, w.y, a11);
        }
        __syncthreads();
    }
    int r = r0 + 2*ty, cc = c0 + 2*cy;
    d_h1[(r+0)*256 + cc+0] = fmaxf(a00, 0.f);
    d_h1[(r+0)*256 + cc+1] = fmaxf(a01, 0.f);
    d_h1[(r+1)*256 + cc+0] = fmaxf(a10, 0.f);
    d_h1[(r+1)*256 + cc+1] = fmaxf(a11, 0.f);
}

__global__ void k_gemm2(const float* __restrict__ w2, const float* __restrict__ b2)
{
    __shared__ float As[32][34];
    __shared__ float Ws[32][36];
    int r0 = blockIdx.y * 32, c0 = blockIdx.x * 32;
    int tid = threadIdx.x;
    int alr = tid >> 3, al4 = (tid & 7) * 4;
    int ty = tid >> 4, cy = tid & 15;

    float2 bias = *(const float2*)&b2[c0 + 2*cy];
    float a00 = bias.x, a01 = bias.y, a10 = bias.x, a11 = bias.y;

    float4 ra = *(const float4*)&d_h1[(r0 + alr)*256 + al4];
    float4 rw = *(const float4*)&w2[alr*256 + c0 + al4];

    for (int kt = 0; kt < 8; kt++) {
        As[al4+0][alr] = ra.x; As[al4+1][alr] = ra.y;
        As[al4+2][alr] = ra.z; As[al4+3][alr] = ra.w;
        *(float4*)&Ws[alr][al4] = rw;
        __syncthreads();
        if (kt < 7) {
            ra = *(const float4*)&d_h1[(r0 + alr)*256 + (kt+1)*32 + al4];
            rw = *(const float4*)&w2[((kt+1)*32 + alr)*256 + c0 + al4];
        }
        #pragma unroll
        for (int k = 0; k < 32; k++) {
            float2 a = *(const float2*)&As[k][2*ty];
            float2 w = *(const float2*)&Ws[k][2*cy];
            a00 = fmaf(a.x, w.x, a00); a01 = fmaf(a.x, w.y, a01);
            a10 = fmaf(a.y, w.x, a10); a11 = fmaf(a.y, w.y, a11);
        }
        __syncthreads();
    }
    int r = r0 + 2*ty, cc = c0 + 2*cy;
    d_h2[(r+0)*256 + cc+0] = fmaxf(a00, 0.f);
    d_h2[(r+0)*256 + cc+1] = fmaxf(a01, 0.f);
    d_h2[(r+1)*256 + cc+0] = fmaxf(a10, 0.f);
    d_h2[(r+1)*256 + cc+1] = fmaxf(a11, 0.f);
}

__global__ void k_gemm3(const float* __restrict__ w3, const float* __restrict__ b3)
{
    __shared__ float As[32][34];
    __shared__ float Ws[32][36];
    int r0 = blockIdx.y * 32, c0 = blockIdx.x * 32;
    int tid = threadIdx.x;
    int alr = tid >> 3, al4 = (tid & 7) * 4;
    int ty = tid >> 4, cy = tid & 15;

    float2 bias = *(const float2*)&b3[c0 + 2*cy];
    float a00 = bias.x, a01 = bias.y, a10 = bias.x, a11 = bias.y;

    float4 ra = *(const float4*)&d_h2[(r0 + alr)*256 + al4];
    float4 rw = *(const float4*)&w3[alr*96 + c0 + al4];

    for (int kt = 0; kt < 8; kt++) {
        As[al4+0][alr] = ra.x; As[al4+1][alr] = ra.y;
        As[al4+2][alr] = ra.z; As[al4+3][alr] = ra.w;
        *(float4*)&Ws[alr][al4] = rw;
        __syncthreads();
        if (kt < 7) {
            ra = *(const float4*)&d_h2[(r0 + alr)*256 + (kt+1)*32 + al4];
            rw = *(const float4*)&w3[((kt+1)*32 + alr)*96 + c0 + al4];
        }
        #pragma unroll
        for (int k = 0; k < 32; k++) {
            float2 a = *(const float2*)&As[k][2*ty];
            float2 w = *(const float2*)&Ws[k][2*cy];
            a00 = fmaf(a.x, w.x, a00); a01 = fmaf(a.x, w.y, a01);
            a10 = fmaf(a.y, w.x, a10); a11 = fmaf(a.y, w.y, a11);
        }
        __syncthreads();
    }
    int r = r0 + 2*ty, cc = c0 + 2*cy;
    int b = r >> 6, n = r & 63;
    d_trend_out[(b*PREDn + cc+0)*Nn + n]     = a00;
    d_trend_out[(b*PREDn + cc+1)*Nn + n]     = a01;
    d_trend_out[(b*PREDn + cc+0)*Nn + n + 1] = a10;
    d_trend_out[(b*PREDn + cc+1)*Nn + n + 1] = a11;
}

// ---------------- CEM: widened DFT (all 256 threads), rest unchanged ----------------
__global__ void __launch_bounds__(256) k_cem()
{
    __shared__ float  resv[64];
    __shared__ float2 tw2[64];
    __shared__ float2 Fs[32];
    __shared__ float  aMag[32];
    __shared__ float2 part[8][32];
    __shared__ float2 g2s[32][8];
    __shared__ float  sMaxA;
    int bt = blockIdx.x;
    int tid = threadIdx.x;

    if (tid < 64) { resv[tid] = d_res[bt*64 + tid]; tw2[tid] = d_TW64[tid]; }
    __syncthreads();

    {
        int m = tid & 31, q = tid >> 5;   // q: 8-way split over n
        float re = 0.f, im = 0.f;
        int k = (m * (q*8)) & 63;
        #pragma unroll
        for (int j = 0; j < 8; j++) {
            float v = resv[q*8 + j];
            float2 t = tw2[k];
            re = fmaf(v,  t.x, re);
            im = fmaf(v, -t.y, im);
            k = (k + m) & 63;
        }
        part[q][m] = make_float2(re, im);
    }
    __syncthreads();
    if (tid < 32) {
        float re = 0.f, im = 0.f;
        #pragma unroll
        for (int q = 0; q < 8; q++) { float2 p = part[q][tid]; re += p.x; im += p.y; }
        Fs[tid] = make_float2(re, im);
        float mag = sqrtf(re*re + im*im);
        aMag[tid] = mag;
        #pragma unroll
        for (int o = 16; o; o >>= 1) mag = fmaxf(mag, __shfl_xor_sync(0xffffffffu, mag, o));
        if (tid == 0) sMaxA = mag;
    }
    __syncthreads();

    {
        int h = tid >> 5, m = tid & 31;
        float scale = aMag[m] * d_cabs[h] * 0.25f;
        float mA = sMaxA;
        float denom = 0.f, gre = 0.f, gim = 0.f;
        #pragma unroll 4
        for (int n = 0; n < 32; n++) {
            float p = __expf(scale * (aMag[n] - mA));
            float2 F = Fs[n];
            denom += p;
            gre = fmaf(p, F.x, gre);
            gim = fmaf(p, F.y, gim);
        }
        float sc = (m == 0 ? 1.f : 2.f) / (64.f * denom);
        g2s[m][h] = make_float2(gre * sc, -gim * sc);
    }
    __syncthreads();

    {
        int h = tid & 7, nb = tid >> 3;
        float acc0 = g2s[0][h].x, acc1 = acc0;
        int k = 0;
        #pragma unroll 4
        for (int m = 1; m < 32; m++) {
            k = (k + nb) & 63;
            int k2 = (k + ((m & 1) << 5)) & 63;
            float2 g  = g2s[m][h];
            float2 ta = tw2[k];
            float2 tb = tw2[k2];
            acc0 = fmaf(g.x, ta.x, acc0); acc0 = fmaf(g.y, ta.y, acc0);
            acc1 = fmaf(g.x, tb.x, acc1); acc1 = fmaf(g.y, tb.y, acc1);
        }
        d_G2[bt*512 + nb*8 + h]      = acc0;
        d_G2[bt*512 + (nb+32)*8 + h] = acc1;
    }
}

// ---------------- fused TEM: rfft + attention -> d_z (no final phase, no MLP dep) ----------------
#define HS 68   // H row stride (floats), 16B-aligned rows (68*4=272)
__global__ void __launch_bounds__(256, 2) k_tem()
{
    __shared__ __align__(16) ull sd[256*16];   // 32KB, aliased after DFT
    __shared__ ull twp[512];
    __shared__ float Csh[8][8][8];
    __shared__ float Osh[8][8];

    float* HreT = (float*)sd;                  // [2][8][HS]
    float* HimT = HreT + 2*8*HS;               // [2][8][HS]
    ull*   zpk  = (ull*)(HimT + 2*8*HS);       // [2][64][8]

    int ng = blockIdx.x, b = blockIdx.y;
    int c0 = ng * 16;
    int tid = threadIdx.x;

    for (int i = tid; i < 512; i += 256) twp[i] = d_TWp[i];
    for (int i = tid; i < 512; i += 256) ((float*)Csh)[i] = ((const float*)d_C)[i];
    if (tid < 64) ((float*)Osh)[tid] = ((const float*)d_Otil)[tid];

    // phase A: fold t <-> 512-t into packed (s,d)
    for (int i = tid; i < 1024; i += 256) {
        int t = i >> 2, cc = (i & 3) * 4;
        int tb = (t == 0) ? 256 : 512 - t;
        float4 ga = *(const float4*)&d_G2[(b*512 + t )*512 + c0 + cc];
        float4 gb = *(const float4*)&d_G2[(b*512 + tb)*512 + c0 + cc];
        if (t == 0) {
            sd[cc+0] = pack2(ga.x, gb.x); sd[cc+1] = pack2(ga.y, gb.y);
            sd[cc+2] = pack2(ga.z, gb.z); sd[cc+3] = pack2(ga.w, gb.w);
        } else {
            sd[t*16+cc+0] = pack2(ga.x + gb.x, ga.x - gb.x);
            sd[t*16+cc+1] = pack2(ga.y + gb.y, ga.y - gb.y);
            sd[t*16+cc+2] = pack2(ga.z + gb.z, ga.z - gb.z);
            sd[t*16+cc+3] = pack2(ga.w + gb.w, ga.w - gb.w);
        }
    }
    __syncthreads();

    // phase B: DFT into registers
    int tau = tid >> 2, cq = (tid & 3) * 4;
    ull acc[4];
    {
        float sgn = (tau & 1) ? -1.f : 1.f;
        #pragma unroll
        for (int j = 0; j < 4; j++) {
            float2 sd0 = unpack2(sd[cq + j]);
            acc[j] = pack2(fmaf(sgn, sd0.y, sd0.x), 0.f);
        }
    }
    {
        int k = tau;
        #pragma unroll 4
        for (int t = 1; t < 256; t++) {
            ull w = twp[k];
            ulonglong2 p0 = *(const ulonglong2*)&sd[t*16 + cq];
            ulonglong2 p1 = *(const ulonglong2*)&sd[t*16 + cq + 2];
            acc[0] = ffma2(p0.x, w, acc[0]);
            acc[1] = ffma2(p0.y, w, acc[1]);
            acc[2] = ffma2(p1.x, w, acc[2]);
            acc[3] = ffma2(p1.y, w, acc[3]);
            k = (k + tau) & 511;
        }
    }
    __syncthreads();

    #pragma unroll
    for (int j = 0; j < 4; j++) {
        int col = cq + j, nl = col >> 3, h = col & 7;
        float2 v = unpack2(acc[j]);
        HreT[(nl*8 + h)*HS + tau] = v.x;
        HimT[(nl*8 + h)*HS + tau] = v.y;
    }
    __syncthreads();

    // zeta: z[nl][np][hp] packed
    for (int i = tid; i < 2*64*8; i += 256) {
        int nl = i >> 9, np = (i >> 3) & 63, hp = i & 7;
        float zr = 0.f, zi = 0.f;
        #pragma unroll
        for (int h2 = 0; h2 < 8; h2++) {
            float o = Osh[hp][h2];
            zr = fmaf(HreT[(nl*8 + h2)*HS + np], o, zr);
            zi = fmaf(HimT[(nl*8 + h2)*HS + np], o, zi);
        }
        zpk[(nl*64 + np)*8 + hp] = pack2(zr, zi);
    }
    __syncthreads();

    // attention with chunked softmax (8-np chunks)
    int mq = tid >> 3, hp = tid & 7;
    #pragma unroll
    for (int nl = 0; nl < 2; nl++) {
        const float* HreB = HreT + nl*8*HS;
        const float* HimB = HimT + nl*8*HS;
        #pragma unroll
        for (int mi = 0; mi < 2; mi++) {
            int m = mq + mi*32;
            float uR[8], uI[8];
            #pragma unroll
            for (int h2 = 0; h2 < 8; h2++) { uR[h2] = 0.f; uI[h2] = 0.f; }
            #pragma unroll
            for (int h1 = 0; h1 < 8; h1++) {
                float hr = HreB[h1*HS + m], hi = HimB[h1*HS + m];
                #pragma unroll
                for (int h2 = 0; h2 < 8; h2++) {
                    float c = Csh[hp][h1][h2];
                    uR[h2] = fmaf(hr, c, uR[h2]);
                    uI[h2] = fmaf(hi, c, uI[h2]);
                }
            }
            ull uR2[8], uI2[8];
            #pragma unroll
            for (int h2 = 0; h2 < 8; h2++) {
                uR2[h2] = pack2(uR[h2], uR[h2]);
                uI2[h2] = pack2(uI[h2], uI[h2]);
            }

            float mrun = -1e30f, lrun = 0.f;
            ull az = 0ull;
            const ull* zrow = zpk + nl*64*8 + hp;

            #pragma unroll 2
            for (int ch = 0; ch < 8; ch++) {     // chunks of 8 np = 4 npq
                float s[8];
                #pragma unroll
                for (int j = 0; j < 4; j++) {
                    int npq = ch*4 + j;
                    ull A = 0ull, B = 0ull, Cc = 0ull, D = 0ull;
                    #pragma unroll
                    for (int h2 = 0; h2 < 8; h2++) {
                        ull hr2 = ((const ull*)(HreB + h2*HS))[npq];
                        ull hi2 = ((const ull*)(HimB + h2*HS))[npq];
                        A  = ffma2(hr2, uR2[h2], A);
                        B  = ffma2(hi2, uI2[h2], B);
                        Cc = ffma2(hr2, uI2[h2], Cc);
                        D  = ffma2(hi2, uR2[h2], D);
                    }
                    // q = (A+B)^2 + (D-C)^2 ; |si| sign irrelevant
                    float2 a = unpack2(A), bb = unpack2(B), c = unpack2(Cc), d = unpack2(D);
                    float sr0 = a.x + bb.x, si0 = d.x - c.x;
                    float sr1 = a.y + bb.y, si1 = d.y - c.y;
                    float q0 = fmaf(sr0, sr0, si0*si0);
                    float q1 = fmaf(sr1, sr1, si1*si1);
                    s[2*j+0] = sqrtf(q0) * 0.25f;
                    s[2*j+1] = sqrtf(q1) * 0.25f;
                }
                float cmax = s[0];
                #pragma unroll
                for (int j = 1; j < 8; j++) cmax = fmaxf(cmax, s[j]);
                float mnew = fmaxf(mrun, cmax);
                float corr = __expf(mrun - mnew);
                float psum = 0.f;
                ull pz = 0ull;
                #pragma unroll
                for (int j = 0; j < 8; j++) {
                    float p = __expf(s[j] - mnew);
                    psum += p;
                    pz = ffma2(zrow[(ch*8 + j)*8], pack2(p, p), pz);
                }
                lrun = fmaf(lrun, corr, psum);
                az = ffma2(az, pack2(corr, corr), pz);
                mrun = mnew;
            }
            float inv = 1.f / lrun;
            float2 a = unpack2(az);
            float ar = a.x * inv, ai = a.y * inv;
            #pragma unroll
            for (int off = 4; off >= 1; off >>= 1) {
                ar += __shfl_down_sync(0xffffffffu, ar, off, 8);
                ai += __shfl_down_sync(0xffffffffu, ai, off, 8);
            }
            if (hp == 0) d_z[(b*64 + ng*2 + nl)*64 + m] = make_float2(ar, ai);
        }
    }
}

// ---------------- fuse: irfft fold of z + trend combine ----------------
__global__ void k_fuse(const float* __restrict__ dr_b, const float* __restrict__ out_b,
                       const float* __restrict__ wf, float* __restrict__ out)
{
    __shared__ float zr[64], zi[64];
    int bn = blockIdx.x;
    int b = bn >> 6, n = bn & 63;
    int tid = threadIdx.x; // 96
    if (tid < 64) {
        float2 v = d_z[bn*64 + tid];
        zr[tid] = v.x; zi[tid] = v.y;
    }
    __syncthreads();
    float acc = zr[0] * d_Cw[tid];
    #pragma unroll 4
    for (int tau = 1; tau < 64; tau++) {
        acc = fmaf( 2.f*zr[tau], d_Cw[tau*PREDn + tid], acc);
        acc = fmaf(-2.f*zi[tau], d_Sw[tau*PREDn + tid], acc);
    }
    float xo = acc * (1.f/512.f) + dr_b[0]*d_Cw[tid] + out_b[tid];
    float v  = wf[0]*xo + wf[1]*d_trend_out[(b*PREDn + tid)*Nn + n];
    out[(b*PREDn + tid)*Nn + n] = v;
}

// ---------------- stream/event context ----------------
namespace {
struct GpuCtx {
    cudaStream_t s1 = nullptr, s2 = nullptr;
    cudaEvent_t eFork = nullptr, eRes = nullptr, eMLP = nullptr, eB = nullptr;
    bool ok = false;
    GpuCtx() {
        ok = (cudaStreamCreateWithFlags(&s1, cudaStreamNonBlocking) == cudaSuccess) &&
             (cudaStreamCreateWithFlags(&s2, cudaStreamNonBlocking) == cudaSuccess) &&
             (cudaEventCreateWithFlags(&eFork, cudaEventDisableTiming) == cudaSuccess) &&
             (cudaEventCreateWithFlags(&eRes,  cudaEventDisableTiming) == cudaSuccess) &&
             (cudaEventCreateWithFlags(&eMLP,  cudaEventDisableTiming) == cudaSuccess) &&
             (cudaEventCreateWithFlags(&eB,    cudaEventDisableTiming) == cudaSuccess);
    }
};
GpuCtx g_ctx;
}

// ---------------- launch ----------------
extern "C" void kernel_launch(void* const* d_in, const int* in_sizes, int n_in,
                              void* d_out, int out_size)
{
    const float* x      = (const float*)d_in[0];
    const float* emb    = (const float*)d_in[1];
    const float* dec_w  = (const float*)d_in[2];
    const float* dec_b  = (const float*)d_in[3];
    const float* mlp_w1 = (const float*)d_in[4];
    const float* mlp_b1 = (const float*)d_in[5];
    const float* mlp_w2 = (const float*)d_in[6];
    const float* mlp_b2 = (const float*)d_in[7];
    const float* mlp_w3 = (const float*)d_in[8];
    const float* mlp_b3 = (const float*)d_in[9];
    const float* cWq    = (const float*)d_in[10];
    const float* cWk    = (const float*)d_in[11];
    const float* cWv    = (const float*)d_in[12];
    const float* cWo    = (const float*)d_in[13];
    const float* tWq    = (const float*)d_in[14];
    const float* tWk    = (const float*)d_in[15];
    const float* tWv    = (const float*)d_in[16];
    const float* tWo    = (const float*)d_in[17];
    const float* dr_w   = (const float*)d_in[18];
    const float* dr_b   = (const float*)d_in[19];
    const float* out_w  = (const float*)d_in[20];
    const float* out_b  = (const float*)d_in[21];
    const float* W_fuse = (const float*)d_in[22];
    float* out = (float*)d_out;

    if (g_ctx.ok) {
        cudaEventRecord(g_ctx.eFork, 0);
        cudaStreamWaitEvent(g_ctx.s1, g_ctx.eFork, 0);
        cudaStreamWaitEvent(g_ctx.s2, g_ctx.eFork, 0);

        // s1: trend branch
        k_decomp<<<dim3(16, 8), 512, 0, g_ctx.s1>>>(x, dec_w, dec_b);
        cudaEventRecord(g_ctx.eRes, g_ctx.s1);
        k_gemm1<<<dim3(8, 16), 256, 0, g_ctx.s1>>>(mlp_w1, mlp_b1);
        k_gemm2<<<dim3(8, 16), 256, 0, g_ctx.s1>>>(mlp_w2, mlp_b2);
        k_gemm3<<<dim3(3, 16), 256, 0, g_ctx.s1>>>(mlp_w3, mlp_b3);
        cudaEventRecord(g_ctx.eMLP, g_ctx.s1);

        // s2: tem-only params
        k_setupB<<<1, 1024, 0, g_ctx.s2>>>(emb, cWv, cWo, tWq, tWk, tWv, tWo, dr_w);
        cudaEventRecord(g_ctx.eB, g_ctx.s2);

        // s0: setupA -> cwsw -> cem -> tem -> fuse
        k_setupA<<<1, 512>>>(emb, cWq, cWk);
        k_setup_cwsw<<<64, 96>>>(out_w);
        cudaStreamWaitEvent(0, g_ctx.eRes, 0);
        k_cem<<<Bn*Tn, 256>>>();
        cudaStreamWaitEvent(0, g_ctx.eB, 0);
        k_tem<<<dim3(32, 8), 256>>>();
        cudaStreamWaitEvent(0, g_ctx.eMLP, 0);
        k_fuse<<<Bn*Nn, 96>>>(dr_b, out_b, W_fuse, out);
    } else {
        k_setupA<<<1, 512>>>(emb, cWq, cWk);
        k_setupB<<<1, 1024>>>(emb, cWv, cWo, tWq, tWk, tWv, tWo, dr_w);
        k_setup_cwsw<<<64, 96>>>(out_w);
        k_decomp<<<dim3(16, 8), 512>>>(x, dec_w, dec_b);
        k_gemm1<<<dim3(8, 16), 256>>>(mlp_w1, mlp_b1);
        k_gemm2<<<dim3(8, 16), 256>>>(mlp_w2, mlp_b2);
        k_gemm3<<<dim3(3, 16), 256>>>(mlp_w3, mlp_b3);
        k_cem<<<Bn*Tn, 256>>>();
        k_tem<<<dim3(32, 8), 256>>>();
        k_fuse<<<Bn*Nn, 96>>>(dr_b, out_b, W_fuse, out);
    }
}

// round 7
// speedup vs baseline: 1.2398x; 1.1050x over previous
#include <cuda_runtime.h>
#include <math.h>

#define Bn 8
#define Tn 512
#define Nn 64
#define Hn 8
#define Mt 64
#define PREDn 96
#define HIDn 256

#define TWO_PI 6.283185307179586
typedef unsigned long long ull;

// ---------------- f32x2 helpers ----------------
__device__ __forceinline__ ull ffma2(ull a, ull b, ull c) {
    ull d;
    asm("fma.rn.f32x2 %0, %1, %2, %3;" : "=l"(d) : "l"(a), "l"(b), "l"(c));
    return d;
}
__device__ __forceinline__ ull pack2(float x, float y) {
    ull r;
    asm("mov.b64 %0, {%1, %2};" : "=l"(r) : "f"(x), "f"(y));
    return r;
}
__device__ __forceinline__ float2 unpack2(ull v) {
    float2 r;
    asm("mov.b64 {%0, %1}, %2;" : "=f"(r.x), "=f"(r.y) : "l"(v));
    return r;
}

// ---------------- device scratch ----------------
__device__ float  d_res[Bn*Tn*Nn];
__device__ float  d_trend[Bn*Tn*Nn];
__device__ float  d_h1[512*256];
__device__ float  d_h2[512*256];
__device__ float  d_trend_out[Bn*PREDn*Nn];
__device__ float  d_G2[Bn*Tn*Nn*Hn];       // (b,t,(n,h))
__device__ float2 d_z[Bn*Nn*Mt];           // (b,n,tau)

// precomputed small params
__device__ float  d_cabs[Hn];
__device__ float  d_C[Hn][Hn][Hn];
__device__ float  d_Otil[Hn][Hn];
__device__ float2 d_TW64[64];
__device__ ull    d_TWp[512];
__device__ float  d_Cw[Mt*PREDn], d_Sw[Mt*PREDn];

// ---------------- setupA: twiddles + cabs (feeds cem + tem DFT) ----------------
__global__ void k_setupA(const float* __restrict__ emb,
                         const float* __restrict__ cWq, const float* __restrict__ cWk)
{
    __shared__ float eq[128], ek[128];
    int t = threadIdx.x; // 512 threads

    if (t < 64) {
        double a = TWO_PI * (double)t / 64.0;
        d_TW64[t] = make_float2((float)cos(a), (float)sin(a));
    }
    {
        double a = TWO_PI * (double)t / 512.0;
        d_TWp[t] = pack2((float)cos(a), -(float)sin(a));
    }
    if (t < 128) {
        float aq = 0.f, ak = 0.f;
        #pragma unroll 4
        for (int d = 0; d < 128; d++) {
            float e = emb[d];
            aq = fmaf(e, cWq[d*128 + t], aq);
            ak = fmaf(e, cWk[d*128 + t], ak);
        }
        eq[t] = aq; ek[t] = ak;
    }
    __syncthreads();
    if (t < 8) {
        float c = 0.f;
        #pragma unroll
        for (int d = 0; d < 16; d++) c = fmaf(eq[t*16 + d], ek[t*16 + d], c);
        d_cabs[t] = fabsf(c);
    }
}

// ---------------- setupB: C / Otil (feeds tem only) ----------------
__global__ void k_setupB(const float* __restrict__ emb,
                         const float* __restrict__ cWv, const float* __restrict__ cWo,
                         const float* __restrict__ tWq, const float* __restrict__ tWk,
                         const float* __restrict__ tWv, const float* __restrict__ tWo,
                         const float* __restrict__ dr_w)
{
    __shared__ float ev[128], wod[128];
    __shared__ float P[8][128];
    __shared__ float Qg[8][128], Kg[8][128], Vg[8][128];
    int t = threadIdx.x; // 1024 threads

    if (t < 128) {
        float av = 0.f;
        #pragma unroll 4
        for (int d = 0; d < 128; d++) av = fmaf(emb[d], cWv[d*128 + t], av);
        ev[t] = av;
        float s = 0.f;
        #pragma unroll 4
        for (int e = 0; e < 128; e++) s = fmaf(tWo[t*128 + e], dr_w[e], s);
        wod[t] = s;
    }
    __syncthreads();

    {
        int h = t >> 7, e = t & 127;
        float s = 0.f;
        #pragma unroll
        for (int d = 0; d < 16; d++) s = fmaf(ev[h*16 + d], cWo[(h*16 + d)*128 + e], s);
        P[h][e] = s;
    }
    __syncthreads();

    {
        int h = t >> 7, e = t & 127;
        float sq = 0.f, sk = 0.f, sv = 0.f;
        #pragma unroll 4
        for (int d = 0; d < 128; d++) {
            float p = P[h][d];
            sq = fmaf(p, tWq[d*128 + e], sq);
            sk = fmaf(p, tWk[d*128 + e], sk);
            sv = fmaf(p, tWv[d*128 + e], sv);
        }
        Qg[h][e] = sq; Kg[h][e] = sk; Vg[h][e] = sv;
    }
    __syncthreads();

    if (t < 512) {
        int hp = t >> 6, h1 = (t >> 3) & 7, h2 = t & 7;
        float s = 0.f;
        #pragma unroll
        for (int d = 0; d < 16; d++) s = fmaf(Qg[h1][hp*16 + d], Kg[h2][hp*16 + d], s);
        d_C[hp][h1][h2] = s;
    }
    if (t >= 512 && t < 576) {
        int u = t - 512;
        int hp = u >> 3, h2 = u & 7;
        float s = 0.f;
        #pragma unroll
        for (int d = 0; d < 16; d++) s = fmaf(Vg[h2][hp*16 + d], wod[hp*16 + d], s);
        d_Otil[hp][h2] = s;
    }
}

// ---------------- cwsw: self-contained (inline twiddles), off critical path ----------------
__global__ void k_setup_cwsw(const float* __restrict__ out_w)
{
    int tau = blockIdx.x, p = threadIdx.x; // 64 blocks x 96 threads
    float c = 0.f, s = 0.f;
    int k = 0;
    #pragma unroll 4
    for (int t = 0; t < 512; t++) {
        float w = out_w[t*PREDn + p];
        float cs, sn;
        sincospif((float)k * (1.f/256.f), &sn, &cs);
        c = fmaf(cs, w, c);
        s = fmaf(sn, w, s);
        k = (k + tau) & 511;
    }
    d_Cw[tau*PREDn + p] = c;
    d_Sw[tau*PREDn + p] = s;
}

// ---------------- decomposition ----------------
__global__ void k_decomp(const float* __restrict__ x,
                         const float* __restrict__ dec_w, const float* __restrict__ dec_b)
{
    __shared__ float xs[80][64];
    int b = blockIdx.y, t0 = blockIdx.x * 32;
    int tid = threadIdx.x;
    const float* xb = x + b*Tn*Nn;

    for (int i = tid; i < 80*64; i += 512) {
        int row = i >> 6, col = i & 63;
        int tg = t0 - 24 + row;
        tg = tg < 0 ? 0 : (tg > 511 ? 511 : tg);
        xs[row][col] = xb[tg*64 + col];
    }
    __syncthreads();

    float w0 = dec_w[0], w1v = dec_w[1], bb0 = dec_b[0], bb1 = dec_b[1];
    int c = tid >> 6, n = tid & 63;
    int r0 = c * 4;
    float s49 = 0.f, s17 = 0.f;
    #pragma unroll
    for (int j = 0; j < 49; j++) {
        float v = xs[r0 + j][n];
        s49 += v;
        if (j >= 16 && j <= 32) s17 += v;
    }
    #pragma unroll
    for (int s = 0; s < 4; s++) {
        if (s > 0) {
            s49 += xs[r0 + 48 + s][n] - xs[r0 + s - 1][n];
            s17 += xs[r0 + 32 + s][n] - xs[r0 + 15 + s][n];
        }
        float xv = xs[r0 + 24 + s][n];
        float m17 = s17 * (1.f/17.f), m49 = s49 * (1.f/49.f);
        float l0 = fmaf(xv, w0, bb0);
        float l1 = fmaf(xv, w1v, bb1);
        float mx = fmaxf(l0, l1);
        float e0 = __expf(l0 - mx), e1 = __expf(l1 - mx);
        float tr = (m17*e0 + m49*e1) / (e0 + e1);
        int gi = b*Tn*Nn + (t0 + r0 + s)*64 + n;
        d_trend[gi] = tr;
        d_res[gi]   = xv - tr;
    }
}

// ---------------- MLP GEMMs (R3 proven versions) ----------------
__global__ void k_gemm1(const float* __restrict__ w1, const float* __restrict__ b1)
{
    __shared__ float As[32][36];
    __shared__ float Ws[32][36];
    int r0 = blockIdx.y * 32, c0 = blockIdx.x * 32;
    int b = r0 >> 6, n0 = r0 & 32;
    int tid = threadIdx.x;
    int lr = tid >> 3, l4 = (tid & 7) * 4;
    int ty = tid >> 4, cy = tid & 15;

    float2 bias = *(const float2*)&b1[c0 + 2*cy];
    float a00 = bias.x, a01 = bias.y, a10 = bias.x, a11 = bias.y;

    float4 ra = *(const float4*)&d_trend[b*32768 + lr*64 + n0 + l4];
    float4 rw = *(const float4*)&w1[lr*256 + c0 + l4];

    for (int kt = 0; kt < 16; kt++) {
        *(float4*)&As[lr][l4] = ra;
        *(float4*)&Ws[lr][l4] = rw;
        __syncthreads();
        if (kt < 15) {
            int kg = (kt+1)*32 + lr;
            ra = *(const float4*)&d_trend[b*32768 + kg*64 + n0 + l4];
            rw = *(const float4*)&w1[kg*256 + c0 + l4];
        }
        #pragma unroll
        for (int k = 0; k < 32; k++) {
            float2 a = *(const float2*)&As[k][2*ty];
            float2 w = *(const float2*)&Ws[k][2*cy];
            a00 = fmaf(a.x, w.x, a00); a01 = fmaf(a.x, w.y, a01);
            a10 = fmaf(a.y, w.x, a10); a11 = fmaf(a.y, w.y, a11);
        }
        __syncthreads();
    }
    int r = r0 + 2*ty, cc = c0 + 2*cy;
    d_h1[(r+0)*256 + cc+0] = fmaxf(a00, 0.f);
    d_h1[(r+0)*256 + cc+1] = fmaxf(a01, 0.f);
    d_h1[(r+1)*256 + cc+0] = fmaxf(a10, 0.f);
    d_h1[(r+1)*256 + cc+1] = fmaxf(a11, 0.f);
}

__global__ void k_gemm2(const float* __restrict__ w2, const float* __restrict__ b2)
{
    __shared__ float As[32][34];
    __shared__ float Ws[32][36];
    int r0 = blockIdx.y * 32, c0 = blockIdx.x * 32;
    int tid = threadIdx.x;
    int alr = tid >> 3, al4 = (tid & 7) * 4;
    int ty = tid >> 4, cy = tid & 15;

    float2 bias = *(const float2*)&b2[c0 + 2*cy];
    float a00 = bias.x, a01 = bias.y, a10 = bias.x, a11 = bias.y;

    float4 ra = *(const float4*)&d_h1[(r0 + alr)*256 + al4];
    float4 rw = *(const float4*)&w2[alr*256 + c0 + al4];

    for (int kt = 0; kt < 8; kt++) {
        As[al4+0][alr] = ra.x; As[al4+1][alr] = ra.y;
        As[al4+2][alr] = ra.z; As[al4+3][alr] = ra.w;
        *(float4*)&Ws[alr][al4] = rw;
        __syncthreads();
        if (kt < 7) {
            ra = *(const float4*)&d_h1[(r0 + alr)*256 + (kt+1)*32 + al4];
            rw = *(const float4*)&w2[((kt+1)*32 + alr)*256 + c0 + al4];
        }
        #pragma unroll
        for (int k = 0; k < 32; k++) {
            float2 a = *(const float2*)&As[k][2*ty];
            float2 w = *(const float2*)&Ws[k][2*cy];
            a00 = fmaf(a.x, w.x, a00); a01 = fmaf(a.x, w.y, a01);
            a10 = fmaf(a.y, w.x, a10); a11 = fmaf(a.y, w.y, a11);
        }
        __syncthreads();
    }
    int r = r0 + 2*ty, cc = c0 + 2*cy;
    d_h2[(r+0)*256 + cc+0] = fmaxf(a00, 0.f);
    d_h2[(r+0)*256 + cc+1] = fmaxf(a01, 0.f);
    d_h2[(r+1)*256 + cc+0] = fmaxf(a10, 0.f);
    d_h2[(r+1)*256 + cc+1] = fmaxf(a11, 0.f);
}

__global__ void k_gemm3(const float* __restrict__ w3, const float* __restrict__ b3)
{
    __shared__ float As[32][34];
    __shared__ float Ws[32][36];
    int r0 = blockIdx.y * 32, c0 = blockIdx.x * 32;
    int tid = threadIdx.x;
    int alr = tid >> 3, al4 = (tid & 7) * 4;
    int ty = tid >> 4, cy = tid & 15;

    float2 bias = *(const float2*)&b3[c0 + 2*cy];
    float a00 = bias.x, a01 = bias.y, a10 = bias.x, a11 = bias.y;

    float4 ra = *(const float4*)&d_h2[(r0 + alr)*256 + al4];
    float4 rw = *(const float4*)&w3[alr*96 + c0 + al4];

    for (int kt = 0; kt < 8; kt++) {
        As[al4+0][alr] = ra.x; As[al4+1][alr] = ra.y;
        As[al4+2][alr] = ra.z; As[al4+3][alr] = ra.w;
        *(float4*)&Ws[alr][al4] = rw;
        __syncthreads();
        if (kt < 7) {
            ra = *(const float4*)&d_h2[(r0 + alr)*256 + (kt+1)*32 + al4];
            rw = *(const float4*)&w3[((kt+1)*32 + alr)*96 + c0 + al4];
        }
        #pragma unroll
        for (int k = 0; k < 32; k++) {
            float2 a = *(const float2*)&As[k][2*ty];
            float2 w = *(const float2*)&Ws[k][2*cy];
            a00 = fmaf(a.x, w.x, a00); a01 = fmaf(a.x, w.y, a01);
            a10 = fmaf(a.y, w.x, a10); a11 = fmaf(a.y, w.y, a11);
        }
        __syncthreads();
    }
    int r = r0 + 2*ty, cc = c0 + 2*cy;
    int b = r >> 6, n = r & 63;
    d_trend_out[(b*PREDn + cc+0)*Nn + n]     = a00;
    d_trend_out[(b*PREDn + cc+1)*Nn + n]     = a01;
    d_trend_out[(b*PREDn + cc+0)*Nn + n + 1] = a10;
    d_trend_out[(b*PREDn + cc+1)*Nn + n + 1] = a11;
}

// ---------------- CEM (unchanged) ----------------
__global__ void __launch_bounds__(256) k_cem()
{
    __shared__ float  resv[64];
    __shared__ float2 tw2[64];
    __shared__ float2 Fs[32];
    __shared__ float  aMag[32];
    __shared__ float2 part[8][32];
    __shared__ float2 g2s[32][8];
    __shared__ float  sMaxA;
    int bt = blockIdx.x;
    int tid = threadIdx.x;

    if (tid < 64) { resv[tid] = d_res[bt*64 + tid]; tw2[tid] = d_TW64[tid]; }
    __syncthreads();

    {
        int m = tid & 31, q = tid >> 5;
        float re = 0.f, im = 0.f;
        int k = (m * (q*8)) & 63;
        #pragma unroll
        for (int j = 0; j < 8; j++) {
            float v = resv[q*8 + j];
            float2 t = tw2[k];
            re = fmaf(v,  t.x, re);
            im = fmaf(v, -t.y, im);
            k = (k + m) & 63;
        }
        part[q][m] = make_float2(re, im);
    }
    __syncthreads();
    if (tid < 32) {
        float re = 0.f, im = 0.f;
        #pragma unroll
        for (int q = 0; q < 8; q++) { float2 p = part[q][tid]; re += p.x; im += p.y; }
        Fs[tid] = make_float2(re, im);
        float mag = sqrtf(re*re + im*im);
        aMag[tid] = mag;
        #pragma unroll
        for (int o = 16; o; o >>= 1) mag = fmaxf(mag, __shfl_xor_sync(0xffffffffu, mag, o));
        if (tid == 0) sMaxA = mag;
    }
    __syncthreads();

    {
        int h = tid >> 5, m = tid & 31;
        float scale = aMag[m] * d_cabs[h] * 0.25f;
        float mA = sMaxA;
        float denom = 0.f, gre = 0.f, gim = 0.f;
        #pragma unroll 4
        for (int n = 0; n < 32; n++) {
            float p = __expf(scale * (aMag[n] - mA));
            float2 F = Fs[n];
            denom += p;
            gre = fmaf(p, F.x, gre);
            gim = fmaf(p, F.y, gim);
        }
        float sc = (m == 0 ? 1.f : 2.f) / (64.f * denom);
        g2s[m][h] = make_float2(gre * sc, -gim * sc);
    }
    __syncthreads();

    {
        int h = tid & 7, nb = tid >> 3;
        float acc0 = g2s[0][h].x, acc1 = acc0;
        int k = 0;
        #pragma unroll 4
        for (int m = 1; m < 32; m++) {
            k = (k + nb) & 63;
            int k2 = (k + ((m & 1) << 5)) & 63;
            float2 g  = g2s[m][h];
            float2 ta = tw2[k];
            float2 tb = tw2[k2];
            acc0 = fmaf(g.x, ta.x, acc0); acc0 = fmaf(g.y, ta.y, acc0);
            acc1 = fmaf(g.x, tb.x, acc1); acc1 = fmaf(g.y, tb.y, acc1);
        }
        d_G2[bt*512 + nb*8 + h]      = acc0;
        d_G2[bt*512 + (nb+32)*8 + h] = acc1;
    }
}

// ---------------- fused TEM: 1 n per block, packed H layout ----------------
// H packed: Hre_pk[npq][h2] = pack2(H[2npq][h2].re, H[2npq+1][h2].re) (rows 64B)
// z packed: zpk[hp][np] (row stride 66 ull, padded for bank-conflict-free)
__global__ void __launch_bounds__(256) k_tem()
{
    __shared__ __align__(16) ull sd[256*8];    // 16KB; aliased after DFT
    __shared__ ull twp[512];
    __shared__ float Csh[8][8][8];
    __shared__ float Osh[8][8];

    ull* Hre_pk = sd;                 // [32][8]
    ull* Him_pk = sd + 256;           // [32][8]
    ull* zpk    = sd + 512;           // [8][66]
    float* fHre = (float*)Hre_pk;
    float* fHim = (float*)Him_pk;

    int n = blockIdx.x, b = blockIdx.y;
    int tid = threadIdx.x;

    for (int i = tid; i < 512; i += 256) twp[i] = d_TWp[i];
    for (int i = tid; i < 512; i += 256) ((float*)Csh)[i] = ((const float*)d_C)[i];
    if (tid < 64) ((float*)Osh)[tid] = ((const float*)d_Otil)[tid];

    // phase A: fold t <-> 512-t, one out-row per thread
    {
        int t = tid;
        int tb = (t == 0) ? 256 : 512 - t;
        const float* ga = &d_G2[(b*512 + t )*512 + n*8];
        const float* gb = &d_G2[(b*512 + tb)*512 + n*8];
        float4 a0 = *(const float4*)ga,     a1 = *(const float4*)(ga + 4);
        float4 b0 = *(const float4*)gb,     b1 = *(const float4*)(gb + 4);
        ull* dst = &sd[t*8];
        if (t == 0) {
            dst[0] = pack2(a0.x, b0.x); dst[1] = pack2(a0.y, b0.y);
            dst[2] = pack2(a0.z, b0.z); dst[3] = pack2(a0.w, b0.w);
            dst[4] = pack2(a1.x, b1.x); dst[5] = pack2(a1.y, b1.y);
            dst[6] = pack2(a1.z, b1.z); dst[7] = pack2(a1.w, b1.w);
        } else {
            dst[0] = pack2(a0.x + b0.x, a0.x - b0.x);
            dst[1] = pack2(a0.y + b0.y, a0.y - b0.y);
            dst[2] = pack2(a0.z + b0.z, a0.z - b0.z);
            dst[3] = pack2(a0.w + b0.w, a0.w - b0.w);
            dst[4] = pack2(a1.x + b1.x, a1.x - b1.x);
            dst[5] = pack2(a1.y + b1.y, a1.y - b1.y);
            dst[6] = pack2(a1.z + b1.z, a1.z - b1.z);
            dst[7] = pack2(a1.w + b1.w, a1.w - b1.w);
        }
    }
    __syncthreads();

    // phase B: DFT. thread = (tau 0..63, cg 0..3 covering 2 cols each)
    int tau = tid >> 2, cg = (tid & 3) * 2;
    ull acc0, acc1;
    {
        float sgn = (tau & 1) ? -1.f : 1.f;
        float2 s0 = unpack2(sd[cg]);
        float2 s1 = unpack2(sd[cg + 1]);
        acc0 = pack2(fmaf(sgn, s0.y, s0.x), 0.f);
        acc1 = pack2(fmaf(sgn, s1.y, s1.x), 0.f);
    }
    {
        int k = tau;
        #pragma unroll 4
        for (int t = 1; t < 256; t++) {
            ull w = twp[k];
            ulonglong2 p = *(const ulonglong2*)&sd[t*8 + cg];
            acc0 = ffma2(p.x, w, acc0);
            acc1 = ffma2(p.y, w, acc1);
            k = (k + tau) & 511;
        }
    }
    __syncthreads();   // done reading sd

    // write H in packed layout: fHre[(tau>>1)*16 + h*2 + (tau&1)]
    {
        int base = (tau >> 1) * 16 + (tau & 1);
        float2 v0 = unpack2(acc0);
        float2 v1 = unpack2(acc1);
        fHre[base + cg*2]       = v0.x;
        fHim[base + cg*2]       = v0.y;
        fHre[base + (cg+1)*2]   = v1.x;
        fHim[base + (cg+1)*2]   = v1.y;
    }
    __syncthreads();

    // zeta: thread = (npq 0..31, hp 0..7), produces z for np pair
    {
        int npq = tid >> 3, hp = tid & 7;
        const ulonglong2* hr = (const ulonglong2*)(Hre_pk + npq*8);
        const ulonglong2* hi = (const ulonglong2*)(Him_pk + npq*8);
        ull zr2 = 0ull, zi2 = 0ull;
        #pragma unroll
        for (int q = 0; q < 4; q++) {
            ulonglong2 r = hr[q], im = hi[q];
            float o0 = Osh[hp][2*q], o1 = Osh[hp][2*q+1];
            zr2 = ffma2(r.x,  pack2(o0, o0), zr2);
            zr2 = ffma2(r.y,  pack2(o1, o1), zr2);
            zi2 = ffma2(im.x, pack2(o0, o0), zi2);
            zi2 = ffma2(im.y, pack2(o1, o1), zi2);
        }
        float2 zr = unpack2(zr2), zi = unpack2(zi2);
        zpk[hp*66 + 2*npq]     = pack2(zr.x, zi.x);
        zpk[hp*66 + 2*npq + 1] = pack2(zr.y, zi.y);
    }
    __syncthreads();

    // attention: thread = (mq 0..31, hp 0..7), m = mq + mi*32
    int mq = tid >> 3, hp = tid & 7;
    #pragma unroll
    for (int mi = 0; mi < 2; mi++) {
        int m = mq + mi*32;
        // u[m,hp] = sum_h1 H[m][h1] * C[hp][h1][:]
        float uR[8], uI[8];
        #pragma unroll
        for (int h2 = 0; h2 < 8; h2++) { uR[h2] = 0.f; uI[h2] = 0.f; }
        {
            int base = (m >> 1) * 16 + (m & 1);
            #pragma unroll
            for (int h1 = 0; h1 < 8; h1++) {
                float hr = fHre[base + h1*2];
                float hi = fHim[base + h1*2];
                #pragma unroll
                for (int h2 = 0; h2 < 8; h2++) {
                    float c = Csh[hp][h1][h2];
                    uR[h2] = fmaf(hr, c, uR[h2]);
                    uI[h2] = fmaf(hi, c, uI[h2]);
                }
            }
        }
        ull uR2[8], uI2[8];
        #pragma unroll
        for (int h2 = 0; h2 < 8; h2++) {
            uR2[h2] = pack2(uR[h2], uR[h2]);
            uI2[h2] = pack2(uI[h2], uI[h2]);
        }

        float mrun = -1e30f, lrun = 0.f;
        ull az = 0ull;

        #pragma unroll 2
        for (int ch = 0; ch < 8; ch++) {        // 4 npq per chunk
            float s[8];
            ulonglong2 zc[4];
            #pragma unroll
            for (int j = 0; j < 4; j++) {
                int npq = ch*4 + j;
                const ulonglong2* hr = (const ulonglong2*)(Hre_pk + npq*8);
                const ulonglong2* hi = (const ulonglong2*)(Him_pk + npq*8);
                ull A = 0ull, B = 0ull, Cc = 0ull, D = 0ull;
                #pragma unroll
                for (int q = 0; q < 4; q++) {
                    ulonglong2 r = hr[q], im = hi[q];
                    A  = ffma2(r.x,  uR2[2*q],   A);
                    A  = ffma2(r.y,  uR2[2*q+1], A);
                    B  = ffma2(im.x, uI2[2*q],   B);
                    B  = ffma2(im.y, uI2[2*q+1], B);
                    Cc = ffma2(r.x,  uI2[2*q],   Cc);
                    Cc = ffma2(r.y,  uI2[2*q+1], Cc);
                    D  = ffma2(im.x, uR2[2*q],   D);
                    D  = ffma2(im.y, uR2[2*q+1], D);
                }
                float2 a = unpack2(A), bb = unpack2(B), c = unpack2(Cc), d = unpack2(D);
                float sr0 = a.x + bb.x, si0 = d.x - c.x;
                float sr1 = a.y + bb.y, si1 = d.y - c.y;
                s[2*j+0] = sqrtf(fmaf(sr0, sr0, si0*si0)) * 0.25f;
                s[2*j+1] = sqrtf(fmaf(sr1, sr1, si1*si1)) * 0.25f;
                zc[j] = *(const ulonglong2*)&zpk[hp*66 + 2*npq];
            }
            float cmax = s[0];
            #pragma unroll
            for (int j = 1; j < 8; j++) cmax = fmaxf(cmax, s[j]);
            float mnew = fmaxf(mrun, cmax);
            float corr = __expf(mrun - mnew);
            float psum = 0.f;
            ull pz = 0ull;
            #pragma unroll
            for (int j = 0; j < 4; j++) {
                float p0 = __expf(s[2*j+0] - mnew);
                float p1 = __expf(s[2*j+1] - mnew);
                psum += p0 + p1;
                pz = ffma2(zc[j].x, pack2(p0, p0), pz);
                pz = ffma2(zc[j].y, pack2(p1, p1), pz);
            }
            lrun = fmaf(lrun, corr, psum);
            az = ffma2(az, pack2(corr, corr), pz);
            mrun = mnew;
        }
        float inv = 1.f / lrun;
        float2 a = unpack2(az);
        float ar = a.x * inv, ai = a.y * inv;
        #pragma unroll
        for (int off = 4; off >= 1; off >>= 1) {
            ar += __shfl_down_sync(0xffffffffu, ar, off, 8);
            ai += __shfl_down_sync(0xffffffffu, ai, off, 8);
        }
        if (hp == 0) d_z[(b*64 + n)*64 + m] = make_float2(ar, ai);
    }
}

// ---------------- fuse: irfft fold of z + trend combine ----------------
__global__ void k_fuse(const float* __restrict__ dr_b, const float* __restrict__ out_b,
                       const float* __restrict__ wf, float* __restrict__ out)
{
    __shared__ float zr[64], zi[64];
    int bn = blockIdx.x;
    int b = bn >> 6, n = bn & 63;
    int tid = threadIdx.x; // 96
    if (tid < 64) {
        float2 v = d_z[bn*64 + tid];
        zr[tid] = v.x; zi[tid] = v.y;
    }
    __syncthreads();
    float acc = zr[0] * d_Cw[tid];
    #pragma unroll 4
    for (int tau = 1; tau < 64; tau++) {
        acc = fmaf( 2.f*zr[tau], d_Cw[tau*PREDn + tid], acc);
        acc = fmaf(-2.f*zi[tau], d_Sw[tau*PREDn + tid], acc);
    }
    float xo = acc * (1.f/512.f) + dr_b[0]*d_Cw[tid] + out_b[tid];
    float v  = wf[0]*xo + wf[1]*d_trend_out[(b*PREDn + tid)*Nn + n];
    out[(b*PREDn + tid)*Nn + n] = v;
}

// ---------------- stream/event context ----------------
namespace {
struct GpuCtx {
    cudaStream_t s1 = nullptr, s2 = nullptr;
    cudaEvent_t eFork = nullptr, eRes = nullptr, eMLP = nullptr, eB = nullptr, eCW = nullptr;
    bool ok = false;
    GpuCtx() {
        ok = (cudaStreamCreateWithFlags(&s1, cudaStreamNonBlocking) == cudaSuccess) &&
             (cudaStreamCreateWithFlags(&s2, cudaStreamNonBlocking) == cudaSuccess) &&
             (cudaEventCreateWithFlags(&eFork, cudaEventDisableTiming) == cudaSuccess) &&
             (cudaEventCreateWithFlags(&eRes,  cudaEventDisableTiming) == cudaSuccess) &&
             (cudaEventCreateWithFlags(&eMLP,  cudaEventDisableTiming) == cudaSuccess) &&
             (cudaEventCreateWithFlags(&eB,    cudaEventDisableTiming) == cudaSuccess) &&
             (cudaEventCreateWithFlags(&eCW,   cudaEventDisableTiming) == cudaSuccess);
    }
};
GpuCtx g_ctx;
}

// ---------------- launch ----------------
extern "C" void kernel_launch(void* const* d_in, const int* in_sizes, int n_in,
                              void* d_out, int out_size)
{
    const float* x      = (const float*)d_in[0];
    const float* emb    = (const float*)d_in[1];
    const float* dec_w  = (const float*)d_in[2];
    const float* dec_b  = (const float*)d_in[3];
    const float* mlp_w1 = (const float*)d_in[4];
    const float* mlp_b1 = (const float*)d_in[5];
    const float* mlp_w2 = (const float*)d_in[6];
    const float* mlp_b2 = (const float*)d_in[7];
    const float* mlp_w3 = (const float*)d_in[8];
    const float* mlp_b3 = (const float*)d_in[9];
    const float* cWq    = (const float*)d_in[10];
    const float* cWk    = (const float*)d_in[11];
    const float* cWv    = (const float*)d_in[12];
    const float* cWo    = (const float*)d_in[13];
    const float* tWq    = (const float*)d_in[14];
    const float* tWk    = (const float*)d_in[15];
    const float* tWv    = (const float*)d_in[16];
    const float* tWo    = (const float*)d_in[17];
    const float* dr_w   = (const float*)d_in[18];
    const float* dr_b   = (const float*)d_in[19];
    const float* out_w  = (const float*)d_in[20];
    const float* out_b  = (const float*)d_in[21];
    const float* W_fuse = (const float*)d_in[22];
    float* out = (float*)d_out;

    if (g_ctx.ok) {
        cudaEventRecord(g_ctx.eFork, 0);
        cudaStreamWaitEvent(g_ctx.s1, g_ctx.eFork, 0);
        cudaStreamWaitEvent(g_ctx.s2, g_ctx.eFork, 0);

        // s1: trend branch
        k_decomp<<<dim3(16, 8), 512, 0, g_ctx.s1>>>(x, dec_w, dec_b);
        cudaEventRecord(g_ctx.eRes, g_ctx.s1);
        k_gemm1<<<dim3(8, 16), 256, 0, g_ctx.s1>>>(mlp_w1, mlp_b1);
        k_gemm2<<<dim3(8, 16), 256, 0, g_ctx.s1>>>(mlp_w2, mlp_b2);
        k_gemm3<<<dim3(3, 16), 256, 0, g_ctx.s1>>>(mlp_w3, mlp_b3);
        cudaEventRecord(g_ctx.eMLP, g_ctx.s1);

        // s2: tem params + cwsw (both off critical path)
        k_setupB<<<1, 1024, 0, g_ctx.s2>>>(emb, cWv, cWo, tWq, tWk, tWv, tWo, dr_w);
        cudaEventRecord(g_ctx.eB, g_ctx.s2);
        k_setup_cwsw<<<64, 96, 0, g_ctx.s2>>>(out_w);
        cudaEventRecord(g_ctx.eCW, g_ctx.s2);

        // s0: setupA -> cem -> tem -> fuse
        k_setupA<<<1, 512>>>(emb, cWq, cWk);
        cudaStreamWaitEvent(0, g_ctx.eRes, 0);
        k_cem<<<Bn*Tn, 256>>>();
        cudaStreamWaitEvent(0, g_ctx.eB, 0);
        k_tem<<<dim3(64, 8), 256>>>();
        cudaStreamWaitEvent(0, g_ctx.eMLP, 0);
        cudaStreamWaitEvent(0, g_ctx.eCW, 0);
        k_fuse<<<Bn*Nn, 96>>>(dr_b, out_b, W_fuse, out);
    } else {
        k_setupA<<<1, 512>>>(emb, cWq, cWk);
        k_setupB<<<1, 1024>>>(emb, cWv, cWo, tWq, tWk, tWv, tWo, dr_w);
        k_setup_cwsw<<<64, 96>>>(out_w);
        k_decomp<<<dim3(16, 8), 512>>>(x, dec_w, dec_b);
        k_gemm1<<<dim3(8, 16), 256>>>(mlp_w1, mlp_b1);
        k_gemm2<<<dim3(8, 16), 256>>>(mlp_w2, mlp_b2);
        k_gemm3<<<dim3(3, 16), 256>>>(mlp_w3, mlp_b3);
        k_cem<<<Bn*Tn, 256>>>();
        k_tem<<<dim3(64, 8), 256>>>();
        k_fuse<<<Bn*Nn, 96>>>(dr_b, out_b, W_fuse, out);
    }
}